// round 16
// baseline (speedup 1.0000x reference)
#include <cuda_runtime.h>
#include <math.h>

#define BB 8
#define CC 19
#define NN (512*1024)
#define GRID 296              // 148 SMs x 2 CTAs, all co-resident (wave 1)
#define BTH 512
#define TILES 4096            // (BB*NN/2) / BTH float2-tiles  == 2097152/512
#define NBS 10240             // s-bit buckets: (bits(s)>>12) - BASES
#define NBS_USED 8704
#define BASES 0x3F800         // bits(1.0f) >> 12
#define CHS 20                // buckets per thread in select (512*20 = 10240)
#define JB09 227              // bucket containing s = 1/0.9
#define JB09_T 11             // owning thread (227/20)
#define JB09_L 7              // local index (227 - 11*20)
#define FRAC09 0.5556         // fraction of bucket 227 with s < 1/0.9 (conf side)
#define NLL_SCALE 4194304.0f  // 2^22 fixed-point for nll
#define NSEL (BB*CC)          // 152 select slices
#define SEL_SMEM (NBS*4)      // 40 KB dynamic smem

// ---------------- static scratch (zero at load; self-cleaning per replay;
// g_arrive is a monotonic epoch counter and is intentionally never reset) ----
__device__ __align__(16) unsigned g_hist[BB*CC*NBS];   // 6.25 MB u32 counts
__device__ double             g_sum;
__device__ unsigned long long g_cnt;
__device__ unsigned           g_done;
__device__ unsigned           g_arrive;

// nll of bucket j reconstructed from index (bucket midpoint), fixed-point 2^22.
__device__ __forceinline__ unsigned nll_fix(int j) {
    float mid = __uint_as_float((((unsigned)(BASES + j)) << 12) | 2048u);
    return (unsigned)(__logf(mid) * NLL_SCALE);
}

__global__ __launch_bounds__(BTH, 2) void fused(const float* __restrict__ pred,
                                                float* __restrict__ out) {
    extern __shared__ unsigned sm[];    // NBS u32 (40 KB), used in phase 2
    const unsigned long long MASK44 = (1ull << 44) - 1ull;
    int tid = threadIdx.x;
    int bid = blockIdx.x;
    int lane = tid & 31, wid = tid >> 5;

    // ================= PHASE 1: streaming softmax histogram =================
    for (int tile = bid; tile < TILES; tile += GRID) {
        int u = tile * BTH + tid;         // global float2 index, < BB*NN/2
        int b = u >> 18;                  // / (NN/2), < BB
        int t = u & 0x3FFFF;
        const float2* p = (const float2*)(pred + (size_t)b * CC * NN) + t;
        const int cs = NN / 2;

        float2 r[CC];
#pragma unroll
        for (int c = 0; c < CC; c++) r[c] = __ldcs(&p[c * cs]);

#define PROC(FIELD) { \
        float m = r[0].FIELD; \
        _Pragma("unroll") \
        for (int c = 1; c < CC; c++) m = fmaxf(m, r[c].FIELD); \
        int lab = 0; \
        float s = 0.0f; \
        _Pragma("unroll") \
        for (int c = CC - 1; c >= 0; c--) { \
            float x = r[c].FIELD; \
            s += __expf(x - m); \
            if (x == m) lab = c;          /* first occurrence wins */ \
        } \
        unsigned us = __float_as_uint(s); \
        int key = min(max((int)(us >> 12) - BASES, 0), NBS_USED - 1); \
        atomicAdd(&g_hist[((size_t)(b * CC + lab)) * NBS + key], 1u); }

        PROC(x) PROC(y)
#undef PROC
    }

    // ====== software grid barrier: monotonic epoch counter, never reset =====
    __syncthreads();
    if (tid == 0) {
        __threadfence();
        unsigned ticket = atomicAdd(&g_arrive, 1u);
        unsigned target = ticket - (ticket % GRID) + GRID;  // end of my epoch
        while ((int)(atomicAdd(&g_arrive, 0u) - target) < 0) __nanosleep(64);
    }
    __syncthreads();

    // ================= PHASE 2: per-(image,class) select + loss =============
    if (bid >= NSEL) return;
    int bc = bid;
    unsigned* h = &g_hist[(size_t)bc * NBS];
    int t0 = tid * CHS;

    // coalesced 16B stage into smem (L2-hot) + coalesced zero of global slice
    {
        uint4* h4 = (uint4*)h;
        uint4* sm4 = (uint4*)sm;
        uint4 v[5];
#pragma unroll
        for (int j = 0; j < 5; j++) v[j] = h4[tid + j * BTH];
#pragma unroll
        for (int j = 0; j < 5; j++) sm4[tid + j * BTH] = v[j];
        uint4 z; z.x = 0u; z.y = 0u; z.z = 0u; z.w = 0u;
#pragma unroll
        for (int j = 0; j < 5; j++) h4[tid + j * BTH] = z;
    }
    __syncthreads();

    // contiguous chunk; packed u64 = (count << 44) | sum(cnt * nll_fix)
    unsigned hv[CHS];
    unsigned long long chunk = 0ull;
#pragma unroll
    for (int j = 0; j < CHS; j++) {
        hv[j] = sm[t0 + j];
        chunk += ((unsigned long long)hv[j] << 44)
               + (unsigned long long)hv[j] * (unsigned long long)nll_fix(t0 + j);
    }

    // hierarchical scan: warp-inclusive via shfl, then 16 warp totals
    unsigned long long inc = chunk;
#pragma unroll
    for (int d = 1; d < 32; d <<= 1) {
        unsigned long long n = __shfl_up_sync(0xFFFFFFFFu, inc, d);
        if (lane >= d) inc += n;
    }
    __shared__ unsigned long long wtot[16];
    if (lane == 31) wtot[wid] = inc;
    __syncthreads();
    if (wid == 0) {
        unsigned long long w = (lane < 16) ? wtot[lane] : 0ull;
#pragma unroll
        for (int d = 1; d < 16; d <<= 1) {
            unsigned long long n = __shfl_up_sync(0xFFFFFFFFu, w, d);
            if (lane >= d) w += n;
        }
        if (lane < 16) wtot[lane] = w;   // inclusive warp prefix
    }
    __syncthreads();
    unsigned long long warp_excl = (wid > 0) ? wtot[wid - 1] : 0ull;
    unsigned long long pre_pack = warp_excl + (inc - chunk);  // exclusive prefix
    long long total = (long long)(wtot[15] >> 44);
    long long k = (long long)(int)((float)total * 0.66f);  // fp32 trunc = reference

    __shared__ long long s_need, s_thrcnt, s_pcnt09, s_c09cnt;
    __shared__ unsigned long long s_ltnll, s_pnll09, s_c09nll;
    __shared__ double s_thravg;
    __shared__ int s_thr;
    if (tid == 0) { s_thr = NBS; s_need = 0; s_thrcnt = 1; s_thravg = 0.0; s_ltnll = 0; }
    __syncthreads();

    // B1: thread owning the rank-k crossing walks its registers
    long long pre_cnt = (long long)(pre_pack >> 44);
    long long ccnt    = (long long)(chunk >> 44);
    if (k > 0 && pre_cnt < k && pre_cnt + ccnt >= k) {
        long long cum = pre_cnt;
        unsigned long long ltn = pre_pack & MASK44;
#pragma unroll
        for (int j = 0; j < CHS; j++) {
            long long c = (long long)hv[j];
            if (cum < k && cum + c >= k) {
                s_thr = t0 + j; s_need = k - cum;
                s_thrcnt = (c > 0) ? c : 1;
                s_thravg = (double)nll_fix(t0 + j);
                s_ltnll = ltn;
                break;
            }
            ltn += (unsigned long long)hv[j] * (unsigned long long)nll_fix(t0 + j);
            cum += c;
        }
    }
    // B2: thread owning the 0.9-confidence bucket gathers conf-set stats
    if (tid == JB09_T) {
        long long pc = pre_cnt;
        unsigned long long pn = pre_pack & MASK44;
#pragma unroll
        for (int j = 0; j < JB09_L; j++) {
            pc += (long long)hv[j];
            pn += (unsigned long long)hv[j] * (unsigned long long)nll_fix(t0 + j);
        }
        s_pcnt09 = pc; s_pnll09 = pn;
        s_c09cnt = (long long)hv[JB09_L];
        s_c09nll = (unsigned long long)hv[JB09_L] * (unsigned long long)nll_fix(JB09);
    }
    __syncthreads();

    if (tid == 0) {
        const double INV = 1.0 / (double)NLL_SCALE;
        long long cnt_sel = 0; double sum_sel = 0.0;
        if (k > 0 && s_thr > JB09) {
            // threshold prob < 0.9: conf set inside top-k -> selection = top-k
            cnt_sel = k;
            sum_sel = ((double)s_ltnll + (double)s_need * s_thravg) * INV;
        } else if (k > 0 && s_thr == JB09) {
            // tie bucket straddles 0.9: union inside bucket from the low-s end
            double cA = FRAC09 * (double)s_thrcnt;
            double selt = fmax((double)s_need, cA);
            cnt_sel = (k - s_need) + (long long)(selt + 0.5);
            sum_sel = ((double)s_ltnll + selt * s_thravg) * INV;
        } else {
            // k==0, or threshold prob > 0.9 (top-k inside conf set) -> conf set
            double cA = FRAC09 * (double)s_c09cnt;
            cnt_sel = s_pcnt09 + (long long)(cA + 0.5);
            sum_sel = ((double)s_pnll09 + FRAC09 * (double)s_c09nll) * INV;
        }
        if (cnt_sel > 0) {
            atomicAdd(&g_sum, sum_sel);
            atomicAdd(&g_cnt, (unsigned long long)cnt_sel);
        }
        __threadfence();
        unsigned ticket = atomicAdd(&g_done, 1);
        if (ticket == NSEL - 1) {
            double             fs = atomicAdd(&g_sum, 0.0);
            unsigned long long fc = atomicAdd(&g_cnt, 0ull);
            if (fc == 0) fc = 1;
            out[0] = (float)(fs / (double)fc);
            g_sum = 0.0; g_cnt = 0ull; g_done = 0u;   // g_arrive: monotonic, no reset
        }
    }
}

// ---------------- launch ----------------
extern "C" void kernel_launch(void* const* d_in, const int* in_sizes, int n_in,
                              void* d_out, int out_size) {
    const float* pred = (const float*)d_in[0];
    float* out = (float*)d_out;
    fused<<<GRID, BTH, SEL_SMEM>>>(pred, out);
}

// round 17
// speedup vs baseline: 1.0244x; 1.0244x over previous
#include <cuda_runtime.h>
#include <math.h>

#define BB 8
#define CC 19
#define NN (512*1024)
#define GRID 296              // 148 SMs x 2 CTAs, all co-resident (wave 1)
#define BTH 512
#define TILES 8192            // (BB*NN) / BTH pixel-tiles == 4194304/512
#define NBS 10240             // s-bit buckets: (bits(s)>>12) - BASES
#define NBS_USED 8704
#define BASES 0x3F800         // bits(1.0f) >> 12
#define CHS 20                // buckets per thread in select (512*20 = 10240)
#define JB09 227              // bucket containing s = 1/0.9
#define JB09_T 11             // owning thread (227/20)
#define JB09_L 7              // local index (227 - 11*20)
#define FRAC09 0.5556         // fraction of bucket 227 with s < 1/0.9 (conf side)
#define NLL_SCALE 4194304.0f  // 2^22 fixed-point for nll
#define NSEL (BB*CC)          // 152 select slices
#define SEL_SMEM (NBS*4)      // 40 KB dynamic smem

// ---------------- static scratch (zero at load; self-cleaning per replay;
// g_arrive is a monotonic epoch counter and is intentionally never reset) ----
__device__ __align__(16) unsigned g_hist[BB*CC*NBS];   // 6.25 MB u32 counts
__device__ double             g_sum;
__device__ unsigned long long g_cnt;
__device__ unsigned           g_done;
__device__ unsigned           g_arrive;

// nll of bucket j reconstructed from index (bucket midpoint), fixed-point 2^22.
__device__ __forceinline__ unsigned nll_fix(int j) {
    float mid = __uint_as_float((((unsigned)(BASES + j)) << 12) | 2048u);
    return (unsigned)(__logf(mid) * NLL_SCALE);
}

__global__ __launch_bounds__(BTH, 2) void fused(const float* __restrict__ pred,
                                                float* __restrict__ out) {
    extern __shared__ unsigned sm[];    // NBS u32 (40 KB), used in phase 2
    int tid = threadIdx.x;
    int bid = blockIdx.x;
    int lane = tid & 31, wid = tid >> 5;

    // ====== PHASE 1: streaming softmax histogram, ONE pixel per thread ======
    // (scalar loads keep regs ~45 < the 64-reg cap: no spills, full MLP=19)
    for (int tile = bid; tile < TILES; tile += GRID) {
        int u = tile * BTH + tid;         // global pixel index, < BB*NN
        int b = u >> 19;                  // / NN, < BB
        int t = u & (NN - 1);
        const float* p = pred + (size_t)b * CC * NN + t;

        float r[CC];
#pragma unroll
        for (int c = 0; c < CC; c++) r[c] = __ldcs(&p[(size_t)c * NN]);

        float m = r[0];
#pragma unroll
        for (int c = 1; c < CC; c++) m = fmaxf(m, r[c]);
        int lab = 0;
        float s = 0.0f;
#pragma unroll
        for (int c = CC - 1; c >= 0; c--) {
            float x = r[c];
            s += __expf(x - m);
            if (x == m) lab = c;          // first occurrence wins
        }
        unsigned us = __float_as_uint(s);
        int key = min(max((int)(us >> 12) - BASES, 0), NBS_USED - 1);
        atomicAdd(&g_hist[((size_t)(b * CC + lab)) * NBS + key], 1u);
    }

    // ====== software grid barrier: monotonic epoch counter, never reset =====
    __syncthreads();
    if (tid == 0) {
        __threadfence();
        unsigned ticket = atomicAdd(&g_arrive, 1u);
        unsigned target = ticket - (ticket % GRID) + GRID;  // end of my epoch
        while ((int)(atomicAdd(&g_arrive, 0u) - target) < 0) __nanosleep(64);
    }
    __syncthreads();

    // ================= PHASE 2: per-(image,class) select + loss =============
    if (bid >= NSEL) return;
    int bc = bid;
    unsigned* h = &g_hist[(size_t)bc * NBS];
    int t0 = tid * CHS;

    // coalesced 16B stage into smem (L2-hot) + coalesced zero of global slice
    {
        uint4* h4 = (uint4*)h;
        uint4* sm4 = (uint4*)sm;
        uint4 v[5];
#pragma unroll
        for (int j = 0; j < 5; j++) v[j] = h4[tid + j * BTH];
#pragma unroll
        for (int j = 0; j < 5; j++) sm4[tid + j * BTH] = v[j];
        uint4 z; z.x = 0u; z.y = 0u; z.z = 0u; z.w = 0u;
#pragma unroll
        for (int j = 0; j < 5; j++) h4[tid + j * BTH] = z;
    }
    __syncthreads();

    // contiguous chunk from smem; packed u64 = (count<<44) | sum(cnt*nll_fix)
    unsigned long long chunk = 0ull;
#pragma unroll 4
    for (int j = 0; j < CHS; j++) {
        unsigned hv = sm[t0 + j];
        chunk += ((unsigned long long)hv << 44)
               + (unsigned long long)hv * (unsigned long long)nll_fix(t0 + j);
    }

    // hierarchical scan: warp-inclusive via shfl, then 16 warp totals
    const unsigned long long MASK44 = (1ull << 44) - 1ull;
    unsigned long long inc = chunk;
#pragma unroll
    for (int d = 1; d < 32; d <<= 1) {
        unsigned long long n = __shfl_up_sync(0xFFFFFFFFu, inc, d);
        if (lane >= d) inc += n;
    }
    __shared__ unsigned long long wtot[16];
    if (lane == 31) wtot[wid] = inc;
    __syncthreads();
    if (wid == 0) {
        unsigned long long w = (lane < 16) ? wtot[lane] : 0ull;
#pragma unroll
        for (int d = 1; d < 16; d <<= 1) {
            unsigned long long n = __shfl_up_sync(0xFFFFFFFFu, w, d);
            if (lane >= d) w += n;
        }
        if (lane < 16) wtot[lane] = w;   // inclusive warp prefix
    }
    __syncthreads();
    unsigned long long warp_excl = (wid > 0) ? wtot[wid - 1] : 0ull;
    unsigned long long pre_pack = warp_excl + (inc - chunk);  // exclusive prefix
    long long total = (long long)(wtot[15] >> 44);
    long long k = (long long)(int)((float)total * 0.66f);  // fp32 trunc = reference

    __shared__ long long s_need, s_thrcnt, s_pcnt09, s_c09cnt;
    __shared__ unsigned long long s_ltnll, s_pnll09, s_c09nll;
    __shared__ double s_thravg;
    __shared__ int s_thr;
    if (tid == 0) { s_thr = NBS; s_need = 0; s_thrcnt = 1; s_thravg = 0.0; s_ltnll = 0; }
    __syncthreads();

    // B1: thread owning the rank-k crossing walks its smem slice
    long long pre_cnt = (long long)(pre_pack >> 44);
    long long ccnt    = (long long)(chunk >> 44);
    if (k > 0 && pre_cnt < k && pre_cnt + ccnt >= k) {
        long long cum = pre_cnt;
        unsigned long long ltn = pre_pack & MASK44;
        for (int j = 0; j < CHS; j++) {
            unsigned hv = sm[t0 + j];
            long long c = (long long)hv;
            if (cum < k && cum + c >= k) {
                s_thr = t0 + j; s_need = k - cum;
                s_thrcnt = (c > 0) ? c : 1;
                s_thravg = (double)nll_fix(t0 + j);
                s_ltnll = ltn;
                break;
            }
            ltn += (unsigned long long)hv * (unsigned long long)nll_fix(t0 + j);
            cum += c;
        }
    }
    // B2: thread owning the 0.9-confidence bucket gathers conf-set stats
    if (tid == JB09_T) {
        long long pc = pre_cnt;
        unsigned long long pn = pre_pack & MASK44;
        for (int j = 0; j < JB09_L; j++) {
            unsigned hv = sm[t0 + j];
            pc += (long long)hv;
            pn += (unsigned long long)hv * (unsigned long long)nll_fix(t0 + j);
        }
        unsigned h09 = sm[JB09];
        s_pcnt09 = pc; s_pnll09 = pn;
        s_c09cnt = (long long)h09;
        s_c09nll = (unsigned long long)h09 * (unsigned long long)nll_fix(JB09);
    }
    __syncthreads();

    if (tid == 0) {
        const double INV = 1.0 / (double)NLL_SCALE;
        long long cnt_sel = 0; double sum_sel = 0.0;
        if (k > 0 && s_thr > JB09) {
            // threshold prob < 0.9: conf set inside top-k -> selection = top-k
            cnt_sel = k;
            sum_sel = ((double)s_ltnll + (double)s_need * s_thravg) * INV;
        } else if (k > 0 && s_thr == JB09) {
            // tie bucket straddles 0.9: union inside bucket from the low-s end
            double cA = FRAC09 * (double)s_thrcnt;
            double selt = fmax((double)s_need, cA);
            cnt_sel = (k - s_need) + (long long)(selt + 0.5);
            sum_sel = ((double)s_ltnll + selt * s_thravg) * INV;
        } else {
            // k==0, or threshold prob > 0.9 (top-k inside conf set) -> conf set
            double cA = FRAC09 * (double)s_c09cnt;
            cnt_sel = s_pcnt09 + (long long)(cA + 0.5);
            sum_sel = ((double)s_pnll09 + FRAC09 * (double)s_c09nll) * INV;
        }
        if (cnt_sel > 0) {
            atomicAdd(&g_sum, sum_sel);
            atomicAdd(&g_cnt, (unsigned long long)cnt_sel);
        }
        __threadfence();
        unsigned ticket = atomicAdd(&g_done, 1);
        if (ticket == NSEL - 1) {
            double             fs = atomicAdd(&g_sum, 0.0);
            unsigned long long fc = atomicAdd(&g_cnt, 0ull);
            if (fc == 0) fc = 1;
            out[0] = (float)(fs / (double)fc);
            g_sum = 0.0; g_cnt = 0ull; g_done = 0u;   // g_arrive: monotonic
        }
    }
}

// ---------------- launch ----------------
extern "C" void kernel_launch(void* const* d_in, const int* in_sizes, int n_in,
                              void* d_out, int out_size) {
    const float* pred = (const float*)d_in[0];
    float* out = (float*)d_out;
    fused<<<GRID, BTH, SEL_SMEM>>>(pred, out);
}